// round 1
// baseline (speedup 1.0000x reference)
#include <cuda_runtime.h>
#include <math.h>

// Problem constants
#define BB 2
#define TT 2048
#define DD 1024
#define HH 16
#define DH 64
#define MM (BB*TT)          // 4096 rows
#define NQKV 3072

// ---------------- scratch (device globals; no allocation allowed) ----------------
__device__ float g_qkv[(size_t)MM * NQKV];     // [M, 3072]  (q|k|v, each [H][dh])
__device__ float g_proj[(size_t)MM * 256];     // [M, 4*64]  cols: arr*64 + h*4 + c
__device__ float g_read6[(size_t)BB * HH * TT * 6];
__device__ float g_jw6[(size_t)BB * HH * TT * 6];
__device__ float g_attn[(size_t)MM * DD];      // attention output [B,T,D]

// ---------------- generic SGEMM: Y[M,N] = A[M,K] @ W[N,K]^T (+bias) ----------------
template<int BM, int BN, int BK, int TM, int TN>
__global__ __launch_bounds__((BM/TM)*(BN/TN))
void sgemm_tn(const float* __restrict__ A, const float* __restrict__ W,
              const float* __restrict__ bias, float* __restrict__ Y,
              int N, int K)
{
    constexpr int TX = BN / TN;
    constexpr int TY = BM / TM;
    constexpr int THREADS = TX * TY;
    constexpr int LDA = BM + 4;
    constexpr int LDB = BN + 4;
    __shared__ float As[BK * LDA];
    __shared__ float Ws[BK * LDB];

    const int tid = threadIdx.x;
    const int tx = tid % TX;
    const int ty = tid / TX;
    const int m0 = blockIdx.y * BM;
    const int n0 = blockIdx.x * BN;

    float acc[TM][TN];
#pragma unroll
    for (int i = 0; i < TM; i++)
#pragma unroll
        for (int j = 0; j < TN; j++) acc[i][j] = 0.f;

    for (int k0 = 0; k0 < K; k0 += BK) {
#pragma unroll
        for (int i = 0; i < (BM * BK) / (4 * THREADS); i++) {
            int li = tid + i * THREADS;
            int row = li / (BK / 4);
            int kq = li % (BK / 4);
            float4 v = *(const float4*)(A + (size_t)(m0 + row) * K + k0 + kq * 4);
            As[(kq * 4 + 0) * LDA + row] = v.x;
            As[(kq * 4 + 1) * LDA + row] = v.y;
            As[(kq * 4 + 2) * LDA + row] = v.z;
            As[(kq * 4 + 3) * LDA + row] = v.w;
        }
#pragma unroll
        for (int i = 0; i < (BN * BK) / (4 * THREADS); i++) {
            int li = tid + i * THREADS;
            int row = li / (BK / 4);
            int kq = li % (BK / 4);
            float4 v = *(const float4*)(W + (size_t)(n0 + row) * K + k0 + kq * 4);
            Ws[(kq * 4 + 0) * LDB + row] = v.x;
            Ws[(kq * 4 + 1) * LDB + row] = v.y;
            Ws[(kq * 4 + 2) * LDB + row] = v.z;
            Ws[(kq * 4 + 3) * LDB + row] = v.w;
        }
        __syncthreads();
#pragma unroll
        for (int kk = 0; kk < BK; kk++) {
            float af[TM], wf[TN];
#pragma unroll
            for (int i = 0; i < TM; i += 4) {
                float4 t = *(const float4*)&As[kk * LDA + ty * TM + i];
                af[i] = t.x; af[i+1] = t.y; af[i+2] = t.z; af[i+3] = t.w;
            }
#pragma unroll
            for (int j = 0; j < TN; j += 4) {
                float4 t = *(const float4*)&Ws[kk * LDB + tx * TN + j];
                wf[j] = t.x; wf[j+1] = t.y; wf[j+2] = t.z; wf[j+3] = t.w;
            }
#pragma unroll
            for (int i = 0; i < TM; i++)
#pragma unroll
                for (int j = 0; j < TN; j++)
                    acc[i][j] = fmaf(af[i], wf[j], acc[i][j]);
        }
        __syncthreads();
    }

    float bj[TN];
#pragma unroll
    for (int j = 0; j < TN; j++) bj[j] = bias ? bias[n0 + tx * TN + j] : 0.f;
#pragma unroll
    for (int i = 0; i < TM; i++) {
        size_t yo = (size_t)(m0 + ty * TM + i) * N + n0 + tx * TN;
#pragma unroll
        for (int j = 0; j < TN; j++)
            Y[yo + j] = acc[i][j] + bj[j];
    }
}

// ---------------- fused 4-way small projection GEMM: N=64 each ----------------
struct WP { const float* w[4]; };

__global__ __launch_bounds__(256)
void proj_gemm(const float* __restrict__ A, WP wp, float* __restrict__ Y, int K)
{
    // BM=128, BN=64, BK=16, TM=8, TN=4; Y is [M][256], this CTA fills cols arr*64..
    constexpr int BM = 128, BN = 64, BK = 16, TM = 8, TN = 4;
    constexpr int TX = BN / TN;     // 16
    constexpr int THREADS = 256;
    constexpr int LDA = BM + 4, LDB = BN + 4;
    __shared__ float As[BK * LDA];
    __shared__ float Ws[BK * LDB];

    const int tid = threadIdx.x;
    const int tx = tid % TX;
    const int ty = tid / TX;
    const int arr = blockIdx.x;            // which weight array
    const int m0 = blockIdx.y * BM;
    const float* __restrict__ W = wp.w[arr];

    float acc[TM][TN];
#pragma unroll
    for (int i = 0; i < TM; i++)
#pragma unroll
        for (int j = 0; j < TN; j++) acc[i][j] = 0.f;

    for (int k0 = 0; k0 < K; k0 += BK) {
#pragma unroll
        for (int i = 0; i < (BM * BK) / (4 * THREADS); i++) {
            int li = tid + i * THREADS;
            int row = li / (BK / 4);
            int kq = li % (BK / 4);
            float4 v = *(const float4*)(A + (size_t)(m0 + row) * K + k0 + kq * 4);
            As[(kq * 4 + 0) * LDA + row] = v.x;
            As[(kq * 4 + 1) * LDA + row] = v.y;
            As[(kq * 4 + 2) * LDA + row] = v.z;
            As[(kq * 4 + 3) * LDA + row] = v.w;
        }
        {
            int li = tid;                   // 64*16/4 = 256 float4 loads
            int row = li / (BK / 4);
            int kq = li % (BK / 4);
            float4 v = *(const float4*)(W + (size_t)row * K + k0 + kq * 4);
            Ws[(kq * 4 + 0) * LDB + row] = v.x;
            Ws[(kq * 4 + 1) * LDB + row] = v.y;
            Ws[(kq * 4 + 2) * LDB + row] = v.z;
            Ws[(kq * 4 + 3) * LDB + row] = v.w;
        }
        __syncthreads();
#pragma unroll
        for (int kk = 0; kk < BK; kk++) {
            float af[TM], wf[TN];
#pragma unroll
            for (int i = 0; i < TM; i += 4) {
                float4 t = *(const float4*)&As[kk * LDA + ty * TM + i];
                af[i] = t.x; af[i+1] = t.y; af[i+2] = t.z; af[i+3] = t.w;
            }
            {
                float4 t = *(const float4*)&Ws[kk * LDB + tx * TN];
                wf[0] = t.x; wf[1] = t.y; wf[2] = t.z; wf[3] = t.w;
            }
#pragma unroll
            for (int i = 0; i < TM; i++)
#pragma unroll
                for (int j = 0; j < TN; j++)
                    acc[i][j] = fmaf(af[i], wf[j], acc[i][j]);
        }
        __syncthreads();
    }

#pragma unroll
    for (int i = 0; i < TM; i++) {
        size_t yo = (size_t)(m0 + ty * TM + i) * 256 + arr * 64 + tx * TN;
#pragma unroll
        for (int j = 0; j < TN; j++)
            Y[yo + j] = acc[i][j];
    }
}

// ---------------- Plücker lines + J6 ----------------
__device__ __forceinline__ void exterior6(const float p1[4], const float p2[4], float L[6])
{
    L[0] = p1[0]*p2[1] - p1[1]*p2[0];
    L[1] = p1[0]*p2[2] - p1[2]*p2[0];
    L[2] = p1[0]*p2[3] - p1[3]*p2[0];
    L[3] = p1[1]*p2[2] - p1[2]*p2[1];
    L[4] = p1[1]*p2[3] - p1[3]*p2[1];
    L[5] = p1[2]*p2[3] - p1[3]*p2[2];
    float n = sqrtf(L[0]*L[0]+L[1]*L[1]+L[2]*L[2]+L[3]*L[3]+L[4]*L[4]+L[5]*L[5]);
    n = fmaxf(n, 1e-12f);
    float inv = 1.f / n;
#pragma unroll
    for (int i = 0; i < 6; i++) L[i] *= inv;
}

__global__ void lines_kernel(const float* __restrict__ proj,
                             float* __restrict__ r6, float* __restrict__ jw6)
{
    int idx = blockIdx.x * blockDim.x + threadIdx.x;
    if (idx >= BB * TT * HH) return;
    int h = idx % HH;
    int t = (idx / HH) % TT;
    int b = idx / (HH * TT);
    int bt = b * TT + t;

    float p1[4] = {0.f, 0.f, 0.f, 0.f};
    if (t > 0) {
#pragma unroll
        for (int c = 0; c < 4; c++)
            p1[c] = proj[(size_t)(bt - 1) * 256 + 0 * 64 + h * 4 + c];
    }
    float p2[4], q1[4], q2[4];
#pragma unroll
    for (int c = 0; c < 4; c++) {
        p2[c] = proj[(size_t)bt * 256 +  64 + h * 4 + c];
        q1[c] = proj[(size_t)bt * 256 + 128 + h * 4 + c];
        q2[c] = proj[(size_t)bt * 256 + 192 + h * 4 + c];
    }
    float L[6];
    exterior6(p1, p2, L);
    size_t o = ((size_t)(b * HH + h) * TT + t) * 6;
    // Jw = L @ J6 = [L5, -L4, L3, L2, -L1, L0]
    jw6[o + 0] =  L[5];
    jw6[o + 1] = -L[4];
    jw6[o + 2] =  L[3];
    jw6[o + 3] =  L[2];
    jw6[o + 4] = -L[1];
    jw6[o + 5] =  L[0];
    exterior6(q1, q2, L);
#pragma unroll
    for (int c = 0; c < 6; c++) r6[o + c] = L[c];
}

// ---------------- flash attention with incidence bias ----------------
#define FLASH_SMEM ((3 * 64 * 68 + 64 * 6) * 4)

__global__ __launch_bounds__(256)
void flash_kernel(const float* __restrict__ qkv,
                  const float* __restrict__ r6,
                  const float* __restrict__ jw6,
                  const float* __restrict__ decay_logits,
                  const float* __restrict__ bias_scale,
                  float* __restrict__ out)
{
    extern __shared__ float sm[];
    float* Qs = sm;                 // [d][q]  stride 68
    float* Ks = Qs + 64 * 68;       // [d][k]  stride 68; reused as P [q][k]
    float* Vs = Ks + 64 * 68;       // [k][d]  stride 68
    float* Jw = Vs + 64 * 68;       // [k][6]

    const int tid = threadIdx.x;
    const int tx = tid & 15;
    const int ty = tid >> 4;
    const int qb = blockIdx.x;
    const int bh = blockIdx.y;
    const int b = bh >> 4;
    const int h = bh & 15;
    const int q0 = qb * 64;
    const float scale = 0.125f;     // 64^-0.5

    const float dec = 1.f / (1.f + __expf(-decay_logits[h]));
    const float logd = __logf(dec);
    const float bsc = bias_scale[h];

    // load Q tile (pre-scaled)
#pragma unroll
    for (int i = 0; i < 16; i++) {
        int idx = tid + i * 256;
        int q = idx >> 6, d = idx & 63;
        Qs[d * 68 + q] = qkv[(size_t)(b * TT + q0 + q) * NQKV + h * 64 + d] * scale;
    }

    // this thread's 4 query rows' read-lines -> regs
    float rq[4][6];
#pragma unroll
    for (int i = 0; i < 4; i++) {
        size_t o = ((size_t)bh * TT + q0 + ty * 4 + i) * 6;
#pragma unroll
        for (int c = 0; c < 6; c++) rq[i][c] = r6[o + c];
    }

    float m_i[4], l_i[4], o_acc[4][4];
#pragma unroll
    for (int i = 0; i < 4; i++) {
        m_i[i] = -1e30f;
        l_i[i] = 0.f;
#pragma unroll
        for (int j = 0; j < 4; j++) o_acc[i][j] = 0.f;
    }

    for (int kb = 0; kb <= qb; kb++) {
        const int k0 = kb * 64;
        __syncthreads();   // previous O-update reads done before overwrite
#pragma unroll
        for (int i = 0; i < 16; i++) {
            int idx = tid + i * 256;
            int k = idx >> 6, d = idx & 63;
            size_t base = (size_t)(b * TT + k0 + k) * NQKV + h * 64 + d;
            Ks[d * 68 + k] = qkv[base + 1024];
            Vs[k * 68 + d] = qkv[base + 2048];
        }
        for (int idx = tid; idx < 384; idx += 256)
            Jw[idx] = jw6[((size_t)bh * TT + k0) * 6 + idx];
        __syncthreads();

        // S = Q K^T (scaled)
        float s[4][4] = {{0.f,0.f,0.f,0.f},{0.f,0.f,0.f,0.f},{0.f,0.f,0.f,0.f},{0.f,0.f,0.f,0.f}};
#pragma unroll 8
        for (int d = 0; d < 64; d++) {
            float4 a  = *(const float4*)&Qs[d * 68 + ty * 4];
            float4 bk = *(const float4*)&Ks[d * 68 + tx * 4];
            s[0][0] = fmaf(a.x, bk.x, s[0][0]); s[0][1] = fmaf(a.x, bk.y, s[0][1]);
            s[0][2] = fmaf(a.x, bk.z, s[0][2]); s[0][3] = fmaf(a.x, bk.w, s[0][3]);
            s[1][0] = fmaf(a.y, bk.x, s[1][0]); s[1][1] = fmaf(a.y, bk.y, s[1][1]);
            s[1][2] = fmaf(a.y, bk.z, s[1][2]); s[1][3] = fmaf(a.y, bk.w, s[1][3]);
            s[2][0] = fmaf(a.z, bk.x, s[2][0]); s[2][1] = fmaf(a.z, bk.y, s[2][1]);
            s[2][2] = fmaf(a.z, bk.z, s[2][2]); s[2][3] = fmaf(a.z, bk.w, s[2][3]);
            s[3][0] = fmaf(a.w, bk.x, s[3][0]); s[3][1] = fmaf(a.w, bk.y, s[3][1]);
            s[3][2] = fmaf(a.w, bk.z, s[3][2]); s[3][3] = fmaf(a.w, bk.w, s[3][3]);
        }

        // bias + mask
        float jwf[4][6];
#pragma unroll
        for (int j = 0; j < 4; j++)
#pragma unroll
            for (int c = 0; c < 6; c++) jwf[j][c] = Jw[(tx * 4 + j) * 6 + c];

#pragma unroll
        for (int i = 0; i < 4; i++) {
            int qg = q0 + ty * 4 + i;
#pragma unroll
            for (int j = 0; j < 4; j++) {
                int kg = k0 + tx * 4 + j;
                if (kg > qg) {
                    s[i][j] = -1e30f;
                } else if (kg < qg) {
                    float inc = rq[i][0]*jwf[j][0] + rq[i][1]*jwf[j][1] + rq[i][2]*jwf[j][2]
                              + rq[i][3]*jwf[j][3] + rq[i][4]*jwf[j][4] + rq[i][5]*jwf[j][5];
                    float w = __expf(logd * (float)(qg - kg));
                    s[i][j] += bsc * w * inc;
                }
            }
        }
        __syncthreads();   // all threads done reading Ks

        // online softmax; P into Ks buffer
#pragma unroll
        for (int i = 0; i < 4; i++) {
            float mx = fmaxf(fmaxf(s[i][0], s[i][1]), fmaxf(s[i][2], s[i][3]));
#pragma unroll
            for (int off = 8; off >= 1; off >>= 1)
                mx = fmaxf(mx, __shfl_xor_sync(0xffffffffu, mx, off, 16));
            float mnew = fmaxf(m_i[i], mx);
            float alpha = __expf(m_i[i] - mnew);
            float rs = 0.f;
#pragma unroll
            for (int j = 0; j < 4; j++) {
                float p = __expf(s[i][j] - mnew);
                s[i][j] = p;
                rs += p;
            }
#pragma unroll
            for (int off = 8; off >= 1; off >>= 1)
                rs += __shfl_xor_sync(0xffffffffu, rs, off, 16);
            l_i[i] = l_i[i] * alpha + rs;
            m_i[i] = mnew;
#pragma unroll
            for (int j = 0; j < 4; j++) {
                o_acc[i][j] *= alpha;
                Ks[(ty * 4 + i) * 68 + tx * 4 + j] = s[i][j];
            }
        }
        __syncthreads();

        // O += P V
#pragma unroll 8
        for (int k = 0; k < 64; k++) {
            float4 v = *(const float4*)&Vs[k * 68 + tx * 4];
#pragma unroll
            for (int i = 0; i < 4; i++) {
                float p = Ks[(ty * 4 + i) * 68 + k];
                o_acc[i][0] = fmaf(p, v.x, o_acc[i][0]);
                o_acc[i][1] = fmaf(p, v.y, o_acc[i][1]);
                o_acc[i][2] = fmaf(p, v.z, o_acc[i][2]);
                o_acc[i][3] = fmaf(p, v.w, o_acc[i][3]);
            }
        }
    }

    // write normalized output: out[b, q, h*64 + d]
#pragma unroll
    for (int i = 0; i < 4; i++) {
        float inv = 1.f / l_i[i];
        size_t oo = (size_t)(b * TT + q0 + ty * 4 + i) * DD + h * 64 + tx * 4;
#pragma unroll
        for (int j = 0; j < 4; j++)
            out[oo + j] = o_acc[i][j] * inv;
    }
}

// ---------------- launch ----------------
extern "C" void kernel_launch(void* const* d_in, const int* in_sizes, int n_in,
                              void* d_out, int out_size)
{
    const float* x      = (const float*)d_in[0];
    const float* w_qkv  = (const float*)d_in[1];
    const float* b_qkv  = (const float*)d_in[2];
    const float* w1w    = (const float*)d_in[3];
    const float* w2w    = (const float*)d_in[4];
    const float* w1r    = (const float*)d_in[5];
    const float* w2r    = (const float*)d_in[6];
    const float* w_out  = (const float*)d_in[7];
    const float* b_out  = (const float*)d_in[8];
    const float* dl     = (const float*)d_in[9];
    const float* bs     = (const float*)d_in[10];

    float *qkvp, *projp, *r6p, *jwp, *attnp;
    cudaGetSymbolAddress((void**)&qkvp,  g_qkv);
    cudaGetSymbolAddress((void**)&projp, g_proj);
    cudaGetSymbolAddress((void**)&r6p,   g_read6);
    cudaGetSymbolAddress((void**)&jwp,   g_jw6);
    cudaGetSymbolAddress((void**)&attnp, g_attn);

    cudaFuncSetAttribute(flash_kernel, cudaFuncAttributeMaxDynamicSharedMemorySize, FLASH_SMEM);

    // 1. QKV projection
    {
        dim3 grid(NQKV / 128, MM / 128);
        sgemm_tn<128,128,16,8,8><<<grid, 256>>>(x, w_qkv, b_qkv, qkvp, NQKV, DD);
    }
    // 2. four small projections (w1_write, w2_write, w1_read, w2_read)
    {
        WP wp;
        wp.w[0] = w1w; wp.w[1] = w2w; wp.w[2] = w1r; wp.w[3] = w2r;
        dim3 grid(4, MM / 128);
        proj_gemm<<<grid, 256>>>(x, wp, projp, DD);
    }
    // 3. Plücker lines + J6
    {
        int n = BB * TT * HH;
        lines_kernel<<<(n + 255) / 256, 256>>>(projp, r6p, jwp);
    }
    // 4. flash attention with incidence bias
    {
        dim3 grid(TT / 64, BB * HH);
        flash_kernel<<<grid, 256, FLASH_SMEM>>>(qkvp, r6p, jwp, dl, bs, attnp);
    }
    // 5. output projection
    {
        dim3 grid(DD / 128, MM / 128);
        sgemm_tn<128,128,16,8,8><<<grid, 256>>>(attnp, w_out, b_out, (float*)d_out, DD, DD);
    }
}

// round 4
// speedup vs baseline: 1.3374x; 1.3374x over previous
#include <cuda_runtime.h>
#include <cuda_bf16.h>
#include <math.h>
#include <stdint.h>

// Problem constants
#define BB 2
#define TT 2048
#define DD 1024
#define HH 16
#define DH 64
#define MM (BB*TT)          // 4096 rows
#define NQKV 3072

// ---------------- scratch (device globals; no allocation allowed) ----------------
__device__ float g_qkv[(size_t)MM * NQKV];
__device__ float g_proj[(size_t)MM * 256];
__device__ float g_read6[(size_t)BB * HH * TT * 6];
__device__ float g_jw6[(size_t)BB * HH * TT * 6];
__device__ float g_attn[(size_t)MM * DD];

__device__ __nv_bfloat16 g_x_hi[(size_t)MM * DD];
__device__ __nv_bfloat16 g_x_lo[(size_t)MM * DD];
__device__ __nv_bfloat16 g_wqkv_hi[(size_t)NQKV * DD];
__device__ __nv_bfloat16 g_wqkv_lo[(size_t)NQKV * DD];
__device__ __nv_bfloat16 g_wout_hi[(size_t)DD * DD];
__device__ __nv_bfloat16 g_wout_lo[(size_t)DD * DD];
__device__ __nv_bfloat16 g_attn_hi[(size_t)MM * DD];
__device__ __nv_bfloat16 g_attn_lo[(size_t)MM * DD];

// ---------------- helpers ----------------
__device__ __forceinline__ uint32_t smem_u32(const void* p) {
    uint32_t a;
    asm("{ .reg .u64 t; cvta.to.shared.u64 t, %1; cvt.u32.u64 %0, t; }" : "=r"(a) : "l"(p));
    return a;
}

#define CP_ASYNC16(saddr, gptr) \
    asm volatile("cp.async.cg.shared.global [%0], [%1], 16;" :: "r"(saddr), "l"(gptr))
#define CP_COMMIT() asm volatile("cp.async.commit_group;")
#define CP_WAIT1()  asm volatile("cp.async.wait_group 1;")
#define CP_WAIT0()  asm volatile("cp.async.wait_group 0;")

#define LDSM_X4(r0, r1, r2, r3, addr) \
    asm volatile("ldmatrix.sync.aligned.m8n8.x4.shared.b16 {%0,%1,%2,%3}, [%4];" \
        : "=r"(r0), "=r"(r1), "=r"(r2), "=r"(r3) : "r"(addr))

#define MMA16816(d, a, b0v, b1v) \
    asm volatile("mma.sync.aligned.m16n8k16.row.col.f32.bf16.bf16.f32 " \
        "{%0,%1,%2,%3}, {%4,%5,%6,%7}, {%8,%9}, {%0,%1,%2,%3};" \
        : "+f"((d)[0]), "+f"((d)[1]), "+f"((d)[2]), "+f"((d)[3]) \
        : "r"((a)[0]), "r"((a)[1]), "r"((a)[2]), "r"((a)[3]), "r"(b0v), "r"(b1v))

// ---------------- hi/lo split conversion ----------------
__global__ void split_kernel(const float* __restrict__ src,
                             __nv_bfloat16* __restrict__ hi,
                             __nv_bfloat16* __restrict__ lo, int n4)
{
    int i = blockIdx.x * blockDim.x + threadIdx.x;
    if (i >= n4) return;
    float4 v = ((const float4*)src)[i];
    __nv_bfloat16 h0 = __float2bfloat16(v.x);
    __nv_bfloat16 h1 = __float2bfloat16(v.y);
    __nv_bfloat16 h2 = __float2bfloat16(v.z);
    __nv_bfloat16 h3 = __float2bfloat16(v.w);
    __nv_bfloat16 l0 = __float2bfloat16(v.x - __bfloat162float(h0));
    __nv_bfloat16 l1 = __float2bfloat16(v.y - __bfloat162float(h1));
    __nv_bfloat16 l2 = __float2bfloat16(v.z - __bfloat162float(h2));
    __nv_bfloat16 l3 = __float2bfloat16(v.w - __bfloat162float(h3));
    __nv_bfloat162* hp = (__nv_bfloat162*)(hi + (size_t)i * 4);
    __nv_bfloat162* lp = (__nv_bfloat162*)(lo + (size_t)i * 4);
    hp[0] = __nv_bfloat162(h0, h1); hp[1] = __nv_bfloat162(h2, h3);
    lp[0] = __nv_bfloat162(l0, l1); lp[1] = __nv_bfloat162(l2, l3);
}

// ---------------- HMMA bf16x3 GEMM: Y[M,N] = A[M,K] @ W[N,K]^T + bias ----------------
// 128x128 CTA tile, 8 warps (2x4 -> 64x32 each), BK=32, 2-stage cp.async pipeline.
// smem per tile: 128 rows x 40 bf16 (pad 32->40 for conflict-free ldmatrix).
#define TILE_B   10240                    // 128*40*2 bytes
#define STAGE_B  (4 * TILE_B)             // Ah, Al, Bh, Bl
#define GEMM_SMEM (2 * STAGE_B)           // 81920

__global__ __launch_bounds__(256, 1)
void gemm_mma(const __nv_bfloat16* __restrict__ Ah, const __nv_bfloat16* __restrict__ Al,
              const __nv_bfloat16* __restrict__ Bh, const __nv_bfloat16* __restrict__ Bl,
              const float* __restrict__ bias, float* __restrict__ Y, int N, int K)
{
    extern __shared__ char smem[];
    const uint32_t sbase = smem_u32(smem);
    const int tid = threadIdx.x;
    const int lane = tid & 31;
    const int wid = tid >> 5;
    const int warp_m = wid >> 2;          // 0..1 (64 rows each)
    const int warp_n = wid & 3;           // 0..3 (32 cols each)
    const int m0 = blockIdx.y * 128;
    const int n0 = blockIdx.x * 128;

    float acc[4][4][4];
#pragma unroll
    for (int mt = 0; mt < 4; mt++)
#pragma unroll
        for (int nt = 0; nt < 4; nt++)
#pragma unroll
            for (int r = 0; r < 4; r++) acc[mt][nt][r] = 0.f;

    // per-thread load slots: units tid*2, tid*2+1 of 512 16B-units per tile
    const int u0 = tid * 2;
    const int row_u0 = u0 >> 2, q_u0 = u0 & 3;        // q in 16B units (8 bf16)
    const int row_u1 = (u0 + 1) >> 2, q_u1 = (u0 + 1) & 3;

    auto load_stage = [&](int c, int s) {
        const int kb = c * 32;
        const uint32_t sb = sbase + s * STAGE_B;
        {
            size_t ga = (size_t)(m0 + row_u0) * K + kb + q_u0 * 8;
            size_t gb = (size_t)(n0 + row_u0) * K + kb + q_u0 * 8;
            uint32_t so = sb + (row_u0 * 40 + q_u0 * 8) * 2;
            CP_ASYNC16(so,              Ah + ga);
            CP_ASYNC16(so + TILE_B,     Al + ga);
            CP_ASYNC16(so + 2 * TILE_B, Bh + gb);
            CP_ASYNC16(so + 3 * TILE_B, Bl + gb);
        }
        {
            size_t ga = (size_t)(m0 + row_u1) * K + kb + q_u1 * 8;
            size_t gb = (size_t)(n0 + row_u1) * K + kb + q_u1 * 8;
            uint32_t so = sb + (row_u1 * 40 + q_u1 * 8) * 2;
            CP_ASYNC16(so,              Ah + ga);
            CP_ASYNC16(so + TILE_B,     Al + ga);
            CP_ASYNC16(so + 2 * TILE_B, Bh + gb);
            CP_ASYNC16(so + 3 * TILE_B, Bl + gb);
        }
        CP_COMMIT();
    };

    // ldmatrix lane address components (element offsets within a tile)
    const int a_mat = lane >> 3, a_r = lane & 7;
    // A: row = base + (mat&1)*8 + r ; col = ks*16 + (mat>>1)*8
    const int a_row_off = (a_mat & 1) * 8 + a_r;
    const int a_col_off = (a_mat >> 1) * 8;
    // B (non-trans; W[N][K] row-major IS k-contiguous col-major B):
    // n = base + (mat>>1)*8 + r ; k = ks*16 + (mat&1)*8
    const int b_row_off = (a_mat >> 1) * 8 + a_r;
    const int b_col_off = (a_mat & 1) * 8;

    const int nc = K >> 5;
    load_stage(0, 0);

    for (int c = 0; c < nc; c++) {
        const int s = c & 1;
        if (c + 1 < nc) {
            load_stage(c + 1, (c + 1) & 1);
            CP_WAIT1();
        } else {
            CP_WAIT0();
        }
        __syncthreads();

        const uint32_t sb = sbase + s * STAGE_B;
#pragma unroll
        for (int ks = 0; ks < 2; ks++) {
            uint32_t ah[4][4], al[4][4];
#pragma unroll
            for (int mt = 0; mt < 4; mt++) {
                int row = warp_m * 64 + mt * 16 + a_row_off;
                int col = ks * 16 + a_col_off;
                uint32_t ad = sb + (row * 40 + col) * 2;
                LDSM_X4(ah[mt][0], ah[mt][1], ah[mt][2], ah[mt][3], ad);
                LDSM_X4(al[mt][0], al[mt][1], al[mt][2], al[mt][3], ad + TILE_B);
            }
            uint32_t bh[2][4], bl[2][4];
#pragma unroll
            for (int np = 0; np < 2; np++) {
                int nrow = warp_n * 32 + np * 16 + b_row_off;
                int kcol = ks * 16 + b_col_off;
                uint32_t bd = sb + 2 * TILE_B + (nrow * 40 + kcol) * 2;
                LDSM_X4(bh[np][0], bh[np][1], bh[np][2], bh[np][3], bd);
                LDSM_X4(bl[np][0], bl[np][1], bl[np][2], bl[np][3], bd + TILE_B);
            }
#pragma unroll
            for (int mt = 0; mt < 4; mt++) {
#pragma unroll
                for (int nt = 0; nt < 4; nt++) {
                    uint32_t b0h = bh[nt >> 1][(nt & 1) * 2];
                    uint32_t b1h = bh[nt >> 1][(nt & 1) * 2 + 1];
                    uint32_t b0l = bl[nt >> 1][(nt & 1) * 2];
                    uint32_t b1l = bl[nt >> 1][(nt & 1) * 2 + 1];
                    MMA16816(acc[mt][nt], ah[mt], b0h, b1h);
                    MMA16816(acc[mt][nt], ah[mt], b0l, b1l);
                    MMA16816(acc[mt][nt], al[mt], b0h, b1h);
                }
            }
        }
        __syncthreads();
    }

    // epilogue: bias + store
#pragma unroll
    for (int mt = 0; mt < 4; mt++) {
        int rbase = m0 + warp_m * 64 + mt * 16 + (lane >> 2);
#pragma unroll
        for (int nt = 0; nt < 4; nt++) {
            int col = n0 + warp_n * 32 + nt * 8 + (lane & 3) * 2;
            float b0 = bias[col], b1 = bias[col + 1];
            float2 v0 = make_float2(acc[mt][nt][0] + b0, acc[mt][nt][1] + b1);
            float2 v1 = make_float2(acc[mt][nt][2] + b0, acc[mt][nt][3] + b1);
            *(float2*)(Y + (size_t)rbase * N + col) = v0;
            *(float2*)(Y + (size_t)(rbase + 8) * N + col) = v1;
        }
    }
}

// ---------------- fused 4-way small projection GEMM: N=64 each ----------------
struct WP { const float* w[4]; };

__global__ __launch_bounds__(256)
void proj_gemm(const float* __restrict__ A, WP wp, float* __restrict__ Y, int K)
{
    constexpr int BM = 128, BN = 64, BK = 16, TM = 8, TN = 4;
    constexpr int TX = BN / TN;
    constexpr int THREADS = 256;
    constexpr int LDA = BM + 4, LDB = BN + 4;
    __shared__ float As[BK * LDA];
    __shared__ float Ws[BK * LDB];

    const int tid = threadIdx.x;
    const int tx = tid % TX;
    const int ty = tid / TX;
    const int arr = blockIdx.x;
    const int m0 = blockIdx.y * BM;
    const float* __restrict__ W = wp.w[arr];

    float acc[TM][TN];
#pragma unroll
    for (int i = 0; i < TM; i++)
#pragma unroll
        for (int j = 0; j < TN; j++) acc[i][j] = 0.f;

    for (int k0 = 0; k0 < K; k0 += BK) {
#pragma unroll
        for (int i = 0; i < (BM * BK) / (4 * THREADS); i++) {
            int li = tid + i * THREADS;
            int row = li / (BK / 4);
            int kq = li % (BK / 4);
            float4 v = *(const float4*)(A + (size_t)(m0 + row) * K + k0 + kq * 4);
            As[(kq * 4 + 0) * LDA + row] = v.x;
            As[(kq * 4 + 1) * LDA + row] = v.y;
            As[(kq * 4 + 2) * LDA + row] = v.z;
            As[(kq * 4 + 3) * LDA + row] = v.w;
        }
        {
            int li = tid;
            int row = li / (BK / 4);
            int kq = li % (BK / 4);
            float4 v = *(const float4*)(W + (size_t)row * K + k0 + kq * 4);
            Ws[(kq * 4 + 0) * LDB + row] = v.x;
            Ws[(kq * 4 + 1) * LDB + row] = v.y;
            Ws[(kq * 4 + 2) * LDB + row] = v.z;
            Ws[(kq * 4 + 3) * LDB + row] = v.w;
        }
        __syncthreads();
#pragma unroll
        for (int kk = 0; kk < BK; kk++) {
            float af[TM], wf[TN];
#pragma unroll
            for (int i = 0; i < TM; i += 4) {
                float4 t = *(const float4*)&As[kk * LDA + ty * TM + i];
                af[i] = t.x; af[i+1] = t.y; af[i+2] = t.z; af[i+3] = t.w;
            }
            {
                float4 t = *(const float4*)&Ws[kk * LDB + tx * TN];
                wf[0] = t.x; wf[1] = t.y; wf[2] = t.z; wf[3] = t.w;
            }
#pragma unroll
            for (int i = 0; i < TM; i++)
#pragma unroll
                for (int j = 0; j < TN; j++)
                    acc[i][j] = fmaf(af[i], wf[j], acc[i][j]);
        }
        __syncthreads();
    }

#pragma unroll
    for (int i = 0; i < TM; i++) {
        size_t yo = (size_t)(m0 + ty * TM + i) * 256 + arr * 64 + tx * TN;
#pragma unroll
        for (int j = 0; j < TN; j++)
            Y[yo + j] = acc[i][j];
    }
}

// ---------------- Plücker lines + J6 ----------------
__device__ __forceinline__ void exterior6(const float p1[4], const float p2[4], float L[6])
{
    L[0] = p1[0]*p2[1] - p1[1]*p2[0];
    L[1] = p1[0]*p2[2] - p1[2]*p2[0];
    L[2] = p1[0]*p2[3] - p1[3]*p2[0];
    L[3] = p1[1]*p2[2] - p1[2]*p2[1];
    L[4] = p1[1]*p2[3] - p1[3]*p2[1];
    L[5] = p1[2]*p2[3] - p1[3]*p2[2];
    float n = sqrtf(L[0]*L[0]+L[1]*L[1]+L[2]*L[2]+L[3]*L[3]+L[4]*L[4]+L[5]*L[5]);
    n = fmaxf(n, 1e-12f);
    float inv = 1.f / n;
#pragma unroll
    for (int i = 0; i < 6; i++) L[i] *= inv;
}

__global__ void lines_kernel(const float* __restrict__ proj,
                             float* __restrict__ r6, float* __restrict__ jw6)
{
    int idx = blockIdx.x * blockDim.x + threadIdx.x;
    if (idx >= BB * TT * HH) return;
    int h = idx % HH;
    int t = (idx / HH) % TT;
    int b = idx / (HH * TT);
    int bt = b * TT + t;

    float p1[4] = {0.f, 0.f, 0.f, 0.f};
    if (t > 0) {
#pragma unroll
        for (int c = 0; c < 4; c++)
            p1[c] = proj[(size_t)(bt - 1) * 256 + 0 * 64 + h * 4 + c];
    }
    float p2[4], q1[4], q2[4];
#pragma unroll
    for (int c = 0; c < 4; c++) {
        p2[c] = proj[(size_t)bt * 256 +  64 + h * 4 + c];
        q1[c] = proj[(size_t)bt * 256 + 128 + h * 4 + c];
        q2[c] = proj[(size_t)bt * 256 + 192 + h * 4 + c];
    }
    float L[6];
    exterior6(p1, p2, L);
    size_t o = ((size_t)(b * HH + h) * TT + t) * 6;
    jw6[o + 0] =  L[5];
    jw6[o + 1] = -L[4];
    jw6[o + 2] =  L[3];
    jw6[o + 3] =  L[2];
    jw6[o + 4] = -L[1];
    jw6[o + 5] =  L[0];
    exterior6(q1, q2, L);
#pragma unroll
    for (int c = 0; c < 6; c++) r6[o + c] = L[c];
}

// ---------------- flash attention with incidence bias ----------------
#define FLASH_SMEM ((3 * 64 * 68 + 64 * 6) * 4)

__global__ __launch_bounds__(256)
void flash_kernel(const float* __restrict__ qkv,
                  const float* __restrict__ r6,
                  const float* __restrict__ jw6,
                  const float* __restrict__ decay_logits,
                  const float* __restrict__ bias_scale,
                  float* __restrict__ out)
{
    extern __shared__ float sm[];
    float* Qs = sm;
    float* Ks = Qs + 64 * 68;
    float* Vs = Ks + 64 * 68;
    float* Jw = Vs + 64 * 68;

    const int tid = threadIdx.x;
    const int tx = tid & 15;
    const int ty = tid >> 4;
    const int qb = blockIdx.x;
    const int bh = blockIdx.y;
    const int b = bh >> 4;
    const int h = bh & 15;
    const int q0 = qb * 64;
    const float scale = 0.125f;

    const float dec = 1.f / (1.f + __expf(-decay_logits[h]));
    const float logd = __logf(dec);
    const float bsc = bias_scale[h];

#pragma unroll
    for (int i = 0; i < 16; i++) {
        int idx = tid + i * 256;
        int q = idx >> 6, d = idx & 63;
        Qs[d * 68 + q] = qkv[(size_t)(b * TT + q0 + q) * NQKV + h * 64 + d] * scale;
    }

    float rq[4][6];
#pragma unroll
    for (int i = 0; i < 4; i++) {
        size_t o = ((size_t)bh * TT + q0 + ty * 4 + i) * 6;
#pragma unroll
        for (int c = 0; c < 6; c++) rq[i][c] = r6[o + c];
    }

    float m_i[4], l_i[4], o_acc[4][4];
#pragma unroll
    for (int i = 0; i < 4; i++) {
        m_i[i] = -1e30f;
        l_i[i] = 0.f;
#pragma unroll
        for (int j = 0; j < 4; j++) o_acc[i][j] = 0.f;
    }

    for (int kb = 0; kb <= qb; kb++) {
        const int k0 = kb * 64;
        __syncthreads();
#pragma unroll
        for (int i = 0; i < 16; i++) {
            int idx = tid + i * 256;
            int k = idx >> 6, d = idx & 63;
            size_t base = (size_t)(b * TT + k0 + k) * NQKV + h * 64 + d;
            Ks[d * 68 + k] = qkv[base + 1024];
            Vs[k * 68 + d] = qkv[base + 2048];
        }
        for (int idx = tid; idx < 384; idx += 256)
            Jw[idx] = jw6[((size_t)bh * TT + k0) * 6 + idx];
        __syncthreads();

        float s[4][4] = {{0.f,0.f,0.f,0.f},{0.f,0.f,0.f,0.f},{0.f,0.f,0.f,0.f},{0.f,0.f,0.f,0.f}};
#pragma unroll 8
        for (int d = 0; d < 64; d++) {
            float4 a  = *(const float4*)&Qs[d * 68 + ty * 4];
            float4 bk = *(const float4*)&Ks[d * 68 + tx * 4];
            s[0][0] = fmaf(a.x, bk.x, s[0][0]); s[0][1] = fmaf(a.x, bk.y, s[0][1]);
            s[0][2] = fmaf(a.x, bk.z, s[0][2]); s[0][3] = fmaf(a.x, bk.w, s[0][3]);
            s[1][0] = fmaf(a.y, bk.x, s[1][0]); s[1][1] = fmaf(a.y, bk.y, s[1][1]);
            s[1][2] = fmaf(a.y, bk.z, s[1][2]); s[1][3] = fmaf(a.y, bk.w, s[1][3]);
            s[2][0] = fmaf(a.z, bk.x, s[2][0]); s[2][1] = fmaf(a.z, bk.y, s[2][1]);
            s[2][2] = fmaf(a.z, bk.z, s[2][2]); s[2][3] = fmaf(a.z, bk.w, s[2][3]);
            s[3][0] = fmaf(a.w, bk.x, s[3][0]); s[3][1] = fmaf(a.w, bk.y, s[3][1]);
            s[3][2] = fmaf(a.w, bk.z, s[3][2]); s[3][3] = fmaf(a.w, bk.w, s[3][3]);
        }

        float jwf[4][6];
#pragma unroll
        for (int j = 0; j < 4; j++)
#pragma unroll
            for (int c = 0; c < 6; c++) jwf[j][c] = Jw[(tx * 4 + j) * 6 + c];

#pragma unroll
        for (int i = 0; i < 4; i++) {
            int qg = q0 + ty * 4 + i;
#pragma unroll
            for (int j = 0; j < 4; j++) {
                int kg = k0 + tx * 4 + j;
                if (kg > qg) {
                    s[i][j] = -1e30f;
                } else if (kg < qg) {
                    float inc = rq[i][0]*jwf[j][0] + rq[i][1]*jwf[j][1] + rq[i][2]*jwf[j][2]
                              + rq[i][3]*jwf[j][3] + rq[i][4]*jwf[j][4] + rq[i][5]*jwf[j][5];
                    float w = __expf(logd * (float)(qg - kg));
                    s[i][j] += bsc * w * inc;
                }
            }
        }
        __syncthreads();

#pragma unroll
        for (int i = 0; i < 4; i++) {
            float mx = fmaxf(fmaxf(s[i][0], s[i][1]), fmaxf(s[i][2], s[i][3]));
#pragma unroll
            for (int off = 8; off >= 1; off >>= 1)
                mx = fmaxf(mx, __shfl_xor_sync(0xffffffffu, mx, off, 16));
            float mnew = fmaxf(m_i[i], mx);
            float alpha = __expf(m_i[i] - mnew);
            float rs = 0.f;
#pragma unroll
            for (int j = 0; j < 4; j++) {
                float p = __expf(s[i][j] - mnew);
                s[i][j] = p;
                rs += p;
            }
#pragma unroll
            for (int off = 8; off >= 1; off >>= 1)
                rs += __shfl_xor_sync(0xffffffffu, rs, off, 16);
            l_i[i] = l_i[i] * alpha + rs;
            m_i[i] = mnew;
#pragma unroll
            for (int j = 0; j < 4; j++) {
                o_acc[i][j] *= alpha;
                Ks[(ty * 4 + i) * 68 + tx * 4 + j] = s[i][j];
            }
        }
        __syncthreads();

#pragma unroll 8
        for (int k = 0; k < 64; k++) {
            float4 v = *(const float4*)&Vs[k * 68 + tx * 4];
#pragma unroll
            for (int i = 0; i < 4; i++) {
                float p = Ks[(ty * 4 + i) * 68 + k];
                o_acc[i][0] = fmaf(p, v.x, o_acc[i][0]);
                o_acc[i][1] = fmaf(p, v.y, o_acc[i][1]);
                o_acc[i][2] = fmaf(p, v.z, o_acc[i][2]);
                o_acc[i][3] = fmaf(p, v.w, o_acc[i][3]);
            }
        }
    }

#pragma unroll
    for (int i = 0; i < 4; i++) {
        float inv = 1.f / l_i[i];
        size_t oo = (size_t)(b * TT + q0 + ty * 4 + i) * DD + h * 64 + tx * 4;
#pragma unroll
        for (int j = 0; j < 4; j++)
            out[oo + j] = o_acc[i][j] * inv;
    }
}

// ---------------- launch ----------------
extern "C" void kernel_launch(void* const* d_in, const int* in_sizes, int n_in,
                              void* d_out, int out_size)
{
    const float* x      = (const float*)d_in[0];
    const float* w_qkv  = (const float*)d_in[1];
    const float* b_qkv  = (const float*)d_in[2];
    const float* w1w    = (const float*)d_in[3];
    const float* w2w    = (const float*)d_in[4];
    const float* w1r    = (const float*)d_in[5];
    const float* w2r    = (const float*)d_in[6];
    const float* w_out  = (const float*)d_in[7];
    const float* b_out  = (const float*)d_in[8];
    const float* dl     = (const float*)d_in[9];
    const float* bs     = (const float*)d_in[10];

    float *qkvp, *projp, *r6p, *jwp, *attnp;
    __nv_bfloat16 *xh, *xl, *wqh, *wql, *woh, *wol, *ath, *atl;
    cudaGetSymbolAddress((void**)&qkvp,  g_qkv);
    cudaGetSymbolAddress((void**)&projp, g_proj);
    cudaGetSymbolAddress((void**)&r6p,   g_read6);
    cudaGetSymbolAddress((void**)&jwp,   g_jw6);
    cudaGetSymbolAddress((void**)&attnp, g_attn);
    cudaGetSymbolAddress((void**)&xh,  g_x_hi);
    cudaGetSymbolAddress((void**)&xl,  g_x_lo);
    cudaGetSymbolAddress((void**)&wqh, g_wqkv_hi);
    cudaGetSymbolAddress((void**)&wql, g_wqkv_lo);
    cudaGetSymbolAddress((void**)&woh, g_wout_hi);
    cudaGetSymbolAddress((void**)&wol, g_wout_lo);
    cudaGetSymbolAddress((void**)&ath, g_attn_hi);
    cudaGetSymbolAddress((void**)&atl, g_attn_lo);

    cudaFuncSetAttribute(flash_kernel, cudaFuncAttributeMaxDynamicSharedMemorySize, FLASH_SMEM);
    cudaFuncSetAttribute(gemm_mma, cudaFuncAttributeMaxDynamicSharedMemorySize, GEMM_SMEM);

    // 0. hi/lo splits
    {
        int n4;
        n4 = (MM * DD) / 4;
        split_kernel<<<(n4 + 255) / 256, 256>>>(x, xh, xl, n4);
        n4 = (NQKV * DD) / 4;
        split_kernel<<<(n4 + 255) / 256, 256>>>(w_qkv, wqh, wql, n4);
        n4 = (DD * DD) / 4;
        split_kernel<<<(n4 + 255) / 256, 256>>>(w_out, woh, wol, n4);
    }
    // 1. QKV projection (HMMA bf16x3)
    {
        dim3 grid(NQKV / 128, MM / 128);
        gemm_mma<<<grid, 256, GEMM_SMEM>>>(xh, xl, wqh, wql, b_qkv, qkvp, NQKV, DD);
    }
    // 2. four small projections
    {
        WP wp;
        wp.w[0] = w1w; wp.w[1] = w2w; wp.w[2] = w1r; wp.w[3] = w2r;
        dim3 grid(4, MM / 128);
        proj_gemm<<<grid, 256>>>(x, wp, projp, DD);
    }
    // 3. Plücker lines + J6
    {
        int n = BB * TT * HH;
        lines_kernel<<<(n + 255) / 256, 256>>>(projp, r6p, jwp);
    }
    // 4. flash attention with incidence bias
    {
        dim3 grid(TT / 64, BB * HH);
        flash_kernel<<<grid, 256, FLASH_SMEM>>>(qkvp, r6p, jwp, dl, bs, attnp);
    }
    // 5. split attention output, then out-proj (HMMA bf16x3)
    {
        int n4 = (MM * DD) / 4;
        split_kernel<<<(n4 + 255) / 256, 256>>>(attnp, ath, atl, n4);
        dim3 grid(DD / 128, MM / 128);
        gemm_mma<<<grid, 256, GEMM_SMEM>>>(ath, atl, woh, wol, b_out, (float*)d_out, DD, DD);
    }
}

// round 5
// speedup vs baseline: 1.8732x; 1.4006x over previous
#include <cuda_runtime.h>
#include <cuda_bf16.h>
#include <math.h>
#include <stdint.h>

// Problem constants
#define BB 2
#define TT 2048
#define DD 1024
#define HH 16
#define MM (BB*TT)          // 4096 rows
#define NQKV 3072

// ---------------- scratch (device globals; no allocation allowed) ----------------
__device__ float g_proj[(size_t)MM * 256];

__device__ __nv_bfloat16 g_x_hi[(size_t)MM * DD];
__device__ __nv_bfloat16 g_x_lo[(size_t)MM * DD];
__device__ __nv_bfloat16 g_wqkv_hi[(size_t)NQKV * DD];
__device__ __nv_bfloat16 g_wqkv_lo[(size_t)NQKV * DD];
__device__ __nv_bfloat16 g_wout_hi[(size_t)DD * DD];
__device__ __nv_bfloat16 g_wout_lo[(size_t)DD * DD];
__device__ __nv_bfloat16 g_attn_hi[(size_t)MM * DD];
__device__ __nv_bfloat16 g_attn_lo[(size_t)MM * DD];
__device__ __nv_bfloat16 g_qkv_hi[(size_t)MM * NQKV];
__device__ __nv_bfloat16 g_qkv_lo[(size_t)MM * NQKV];
// read-lines / J-write-lines, bf16 hi/lo, layout [bh][t][16] (cols 6..15 zero)
__device__ __nv_bfloat16 g_r6_hi[(size_t)BB * HH * TT * 16];
__device__ __nv_bfloat16 g_r6_lo[(size_t)BB * HH * TT * 16];
__device__ __nv_bfloat16 g_jw_hi[(size_t)BB * HH * TT * 16];
__device__ __nv_bfloat16 g_jw_lo[(size_t)BB * HH * TT * 16];

// ---------------- helpers ----------------
__device__ __forceinline__ uint32_t smem_u32(const void* p) {
    uint32_t a;
    asm("{ .reg .u64 t; cvta.to.shared.u64 t, %1; cvt.u32.u64 %0, t; }" : "=r"(a) : "l"(p));
    return a;
}

#define CP_ASYNC16(saddr, gptr) \
    asm volatile("cp.async.cg.shared.global [%0], [%1], 16;" :: "r"(saddr), "l"(gptr))
#define CP_COMMIT() asm volatile("cp.async.commit_group;")
#define CP_WAIT1()  asm volatile("cp.async.wait_group 1;")
#define CP_WAIT0()  asm volatile("cp.async.wait_group 0;")

#define LDSM_X4(r0, r1, r2, r3, addr) \
    asm volatile("ldmatrix.sync.aligned.m8n8.x4.shared.b16 {%0,%1,%2,%3}, [%4];" \
        : "=r"(r0), "=r"(r1), "=r"(r2), "=r"(r3) : "r"(addr))
#define LDSM_X4_T(r0, r1, r2, r3, addr) \
    asm volatile("ldmatrix.sync.aligned.m8n8.x4.trans.shared.b16 {%0,%1,%2,%3}, [%4];" \
        : "=r"(r0), "=r"(r1), "=r"(r2), "=r"(r3) : "r"(addr))

#define MMA16816(d, a, b0v, b1v) \
    asm volatile("mma.sync.aligned.m16n8k16.row.col.f32.bf16.bf16.f32 " \
        "{%0,%1,%2,%3}, {%4,%5,%6,%7}, {%8,%9}, {%0,%1,%2,%3};" \
        : "+f"((d)[0]), "+f"((d)[1]), "+f"((d)[2]), "+f"((d)[3]) \
        : "r"((a)[0]), "r"((a)[1]), "r"((a)[2]), "r"((a)[3]), "r"(b0v), "r"(b1v))

__device__ __forceinline__ uint32_t pack_bf2(__nv_bfloat16 a, __nv_bfloat16 b) {
    __nv_bfloat162 t(a, b);
    return *(uint32_t*)&t;
}
__device__ __forceinline__ void hilo2(float x, float y, uint32_t& hi, uint32_t& lo) {
    __nv_bfloat16 hx = __float2bfloat16(x), hy = __float2bfloat16(y);
    hi = pack_bf2(hx, hy);
    lo = pack_bf2(__float2bfloat16(x - __bfloat162float(hx)),
                  __float2bfloat16(y - __bfloat162float(hy)));
}
__device__ __forceinline__ void split1(float v, __nv_bfloat16& h, __nv_bfloat16& l) {
    h = __float2bfloat16(v);
    l = __float2bfloat16(v - __bfloat162float(h));
}

// ---------------- hi/lo split conversion ----------------
__global__ void split_kernel(const float* __restrict__ src,
                             __nv_bfloat16* __restrict__ hi,
                             __nv_bfloat16* __restrict__ lo, int n4)
{
    int i = blockIdx.x * blockDim.x + threadIdx.x;
    if (i >= n4) return;
    float4 v = ((const float4*)src)[i];
    __nv_bfloat16 h0, h1, h2, h3, l0, l1, l2, l3;
    split1(v.x, h0, l0); split1(v.y, h1, l1);
    split1(v.z, h2, l2); split1(v.w, h3, l3);
    __nv_bfloat162* hp = (__nv_bfloat162*)(hi + (size_t)i * 4);
    __nv_bfloat162* lp = (__nv_bfloat162*)(lo + (size_t)i * 4);
    hp[0] = __nv_bfloat162(h0, h1); hp[1] = __nv_bfloat162(h2, h3);
    lp[0] = __nv_bfloat162(l0, l1); lp[1] = __nv_bfloat162(l2, l3);
}

// ---------------- HMMA bf16x3 GEMM ----------------
// Y[M,N] = A[M,K] @ W[N,K]^T + bias. Output: fp32 Y, or bf16 hi/lo split pair.
#define TILE_B   10240
#define STAGE_B  (4 * TILE_B)
#define GEMM_SMEM (2 * STAGE_B)

__global__ __launch_bounds__(256, 1)
void gemm_mma(const __nv_bfloat16* __restrict__ Ah, const __nv_bfloat16* __restrict__ Al,
              const __nv_bfloat16* __restrict__ Bh, const __nv_bfloat16* __restrict__ Bl,
              const float* __restrict__ bias, float* __restrict__ Y,
              __nv_bfloat16* __restrict__ Yhi, __nv_bfloat16* __restrict__ Ylo,
              int N, int K)
{
    extern __shared__ char smem[];
    const uint32_t sbase = smem_u32(smem);
    const int tid = threadIdx.x;
    const int lane = tid & 31;
    const int wid = tid >> 5;
    const int warp_m = wid >> 2;
    const int warp_n = wid & 3;
    const int m0 = blockIdx.y * 128;
    const int n0 = blockIdx.x * 128;

    float acc[4][4][4];
#pragma unroll
    for (int mt = 0; mt < 4; mt++)
#pragma unroll
        for (int nt = 0; nt < 4; nt++)
#pragma unroll
            for (int r = 0; r < 4; r++) acc[mt][nt][r] = 0.f;

    const int u0 = tid * 2;
    const int row_u0 = u0 >> 2, q_u0 = u0 & 3;
    const int row_u1 = (u0 + 1) >> 2, q_u1 = (u0 + 1) & 3;

    auto load_stage = [&](int c, int s) {
        const int kb = c * 32;
        const uint32_t sb = sbase + s * STAGE_B;
        {
            size_t ga = (size_t)(m0 + row_u0) * K + kb + q_u0 * 8;
            size_t gb = (size_t)(n0 + row_u0) * K + kb + q_u0 * 8;
            uint32_t so = sb + (row_u0 * 40 + q_u0 * 8) * 2;
            CP_ASYNC16(so,              Ah + ga);
            CP_ASYNC16(so + TILE_B,     Al + ga);
            CP_ASYNC16(so + 2 * TILE_B, Bh + gb);
            CP_ASYNC16(so + 3 * TILE_B, Bl + gb);
        }
        {
            size_t ga = (size_t)(m0 + row_u1) * K + kb + q_u1 * 8;
            size_t gb = (size_t)(n0 + row_u1) * K + kb + q_u1 * 8;
            uint32_t so = sb + (row_u1 * 40 + q_u1 * 8) * 2;
            CP_ASYNC16(so,              Ah + ga);
            CP_ASYNC16(so + TILE_B,     Al + ga);
            CP_ASYNC16(so + 2 * TILE_B, Bh + gb);
            CP_ASYNC16(so + 3 * TILE_B, Bl + gb);
        }
        CP_COMMIT();
    };

    const int a_mat = lane >> 3, a_r = lane & 7;
    const int a_row_off = (a_mat & 1) * 8 + a_r;
    const int a_col_off = (a_mat >> 1) * 8;
    const int b_row_off = (a_mat >> 1) * 8 + a_r;
    const int b_col_off = (a_mat & 1) * 8;

    const int nc = K >> 5;
    load_stage(0, 0);

    for (int c = 0; c < nc; c++) {
        const int s = c & 1;
        if (c + 1 < nc) {
            load_stage(c + 1, (c + 1) & 1);
            CP_WAIT1();
        } else {
            CP_WAIT0();
        }
        __syncthreads();

        const uint32_t sb = sbase + s * STAGE_B;
#pragma unroll
        for (int ks = 0; ks < 2; ks++) {
            uint32_t ah[4][4], al[4][4];
#pragma unroll
            for (int mt = 0; mt < 4; mt++) {
                int row = warp_m * 64 + mt * 16 + a_row_off;
                int col = ks * 16 + a_col_off;
                uint32_t ad = sb + (row * 40 + col) * 2;
                LDSM_X4(ah[mt][0], ah[mt][1], ah[mt][2], ah[mt][3], ad);
                LDSM_X4(al[mt][0], al[mt][1], al[mt][2], al[mt][3], ad + TILE_B);
            }
            uint32_t bh[2][4], bl[2][4];
#pragma unroll
            for (int np = 0; np < 2; np++) {
                int nrow = warp_n * 32 + np * 16 + b_row_off;
                int kcol = ks * 16 + b_col_off;
                uint32_t bd = sb + 2 * TILE_B + (nrow * 40 + kcol) * 2;
                LDSM_X4(bh[np][0], bh[np][1], bh[np][2], bh[np][3], bd);
                LDSM_X4(bl[np][0], bl[np][1], bl[np][2], bl[np][3], bd + TILE_B);
            }
#pragma unroll
            for (int mt = 0; mt < 4; mt++) {
#pragma unroll
                for (int nt = 0; nt < 4; nt++) {
                    uint32_t b0h = bh[nt >> 1][(nt & 1) * 2];
                    uint32_t b1h = bh[nt >> 1][(nt & 1) * 2 + 1];
                    uint32_t b0l = bl[nt >> 1][(nt & 1) * 2];
                    uint32_t b1l = bl[nt >> 1][(nt & 1) * 2 + 1];
                    MMA16816(acc[mt][nt], ah[mt], b0h, b1h);
                    MMA16816(acc[mt][nt], ah[mt], b0l, b1l);
                    MMA16816(acc[mt][nt], al[mt], b0h, b1h);
                }
            }
        }
        __syncthreads();
    }

    // epilogue
#pragma unroll
    for (int mt = 0; mt < 4; mt++) {
        int rbase = m0 + warp_m * 64 + mt * 16 + (lane >> 2);
#pragma unroll
        for (int nt = 0; nt < 4; nt++) {
            int col = n0 + warp_n * 32 + nt * 8 + (lane & 3) * 2;
            float b0 = bias[col], b1 = bias[col + 1];
            float v0 = acc[mt][nt][0] + b0, v1 = acc[mt][nt][1] + b1;
            float v2 = acc[mt][nt][2] + b0, v3 = acc[mt][nt][3] + b1;
            if (Yhi) {
                uint32_t h01, l01, h23, l23;
                hilo2(v0, v1, h01, l01);
                hilo2(v2, v3, h23, l23);
                *(uint32_t*)(Yhi + (size_t)rbase * N + col) = h01;
                *(uint32_t*)(Ylo + (size_t)rbase * N + col) = l01;
                *(uint32_t*)(Yhi + (size_t)(rbase + 8) * N + col) = h23;
                *(uint32_t*)(Ylo + (size_t)(rbase + 8) * N + col) = l23;
            } else {
                *(float2*)(Y + (size_t)rbase * N + col) = make_float2(v0, v1);
                *(float2*)(Y + (size_t)(rbase + 8) * N + col) = make_float2(v2, v3);
            }
        }
    }
}

// ---------------- fused 4-way small projection GEMM: N=64 each ----------------
struct WP { const float* w[4]; };

__global__ __launch_bounds__(256)
void proj_gemm(const float* __restrict__ A, WP wp, float* __restrict__ Y, int K)
{
    constexpr int BM = 128, BN = 64, BK = 16, TM = 8, TN = 4;
    constexpr int TX = BN / TN;
    constexpr int THREADS = 256;
    constexpr int LDA = BM + 4, LDB = BN + 4;
    __shared__ float As[BK * LDA];
    __shared__ float Ws[BK * LDB];

    const int tid = threadIdx.x;
    const int tx = tid % TX;
    const int ty = tid / TX;
    const int arr = blockIdx.x;
    const int m0 = blockIdx.y * BM;
    const float* __restrict__ W = wp.w[arr];

    float acc[TM][TN];
#pragma unroll
    for (int i = 0; i < TM; i++)
#pragma unroll
        for (int j = 0; j < TN; j++) acc[i][j] = 0.f;

    for (int k0 = 0; k0 < K; k0 += BK) {
#pragma unroll
        for (int i = 0; i < (BM * BK) / (4 * THREADS); i++) {
            int li = tid + i * THREADS;
            int row = li / (BK / 4);
            int kq = li % (BK / 4);
            float4 v = *(const float4*)(A + (size_t)(m0 + row) * K + k0 + kq * 4);
            As[(kq * 4 + 0) * LDA + row] = v.x;
            As[(kq * 4 + 1) * LDA + row] = v.y;
            As[(kq * 4 + 2) * LDA + row] = v.z;
            As[(kq * 4 + 3) * LDA + row] = v.w;
        }
        {
            int li = tid;
            int row = li / (BK / 4);
            int kq = li % (BK / 4);
            float4 v = *(const float4*)(W + (size_t)row * K + k0 + kq * 4);
            Ws[(kq * 4 + 0) * LDB + row] = v.x;
            Ws[(kq * 4 + 1) * LDB + row] = v.y;
            Ws[(kq * 4 + 2) * LDB + row] = v.z;
            Ws[(kq * 4 + 3) * LDB + row] = v.w;
        }
        __syncthreads();
#pragma unroll
        for (int kk = 0; kk < BK; kk++) {
            float af[TM], wf[TN];
#pragma unroll
            for (int i = 0; i < TM; i += 4) {
                float4 t = *(const float4*)&As[kk * LDA + ty * TM + i];
                af[i] = t.x; af[i+1] = t.y; af[i+2] = t.z; af[i+3] = t.w;
            }
            {
                float4 t = *(const float4*)&Ws[kk * LDB + tx * TN];
                wf[0] = t.x; wf[1] = t.y; wf[2] = t.z; wf[3] = t.w;
            }
#pragma unroll
            for (int i = 0; i < TM; i++)
#pragma unroll
                for (int j = 0; j < TN; j++)
                    acc[i][j] = fmaf(af[i], wf[j], acc[i][j]);
        }
        __syncthreads();
    }

#pragma unroll
    for (int i = 0; i < TM; i++) {
        size_t yo = (size_t)(m0 + ty * TM + i) * 256 + arr * 64 + tx * TN;
#pragma unroll
        for (int j = 0; j < TN; j++)
            Y[yo + j] = acc[i][j];
    }
}

// ---------------- Plücker lines + J6 -> bf16 hi/lo padded ----------------
__device__ __forceinline__ void exterior6(const float p1[4], const float p2[4], float L[6])
{
    L[0] = p1[0]*p2[1] - p1[1]*p2[0];
    L[1] = p1[0]*p2[2] - p1[2]*p2[0];
    L[2] = p1[0]*p2[3] - p1[3]*p2[0];
    L[3] = p1[1]*p2[2] - p1[2]*p2[1];
    L[4] = p1[1]*p2[3] - p1[3]*p2[1];
    L[5] = p1[2]*p2[3] - p1[3]*p2[2];
    float n = sqrtf(L[0]*L[0]+L[1]*L[1]+L[2]*L[2]+L[3]*L[3]+L[4]*L[4]+L[5]*L[5]);
    n = fmaxf(n, 1e-12f);
    float inv = 1.f / n;
#pragma unroll
    for (int i = 0; i < 6; i++) L[i] *= inv;
}

__global__ void lines_kernel(const float* __restrict__ proj,
                             __nv_bfloat16* __restrict__ r6h, __nv_bfloat16* __restrict__ r6l,
                             __nv_bfloat16* __restrict__ jwh, __nv_bfloat16* __restrict__ jwl)
{
    int idx = blockIdx.x * blockDim.x + threadIdx.x;
    if (idx >= BB * TT * HH) return;
    int h = idx % HH;
    int t = (idx / HH) % TT;
    int b = idx / (HH * TT);
    int bt = b * TT + t;

    float p1[4] = {0.f, 0.f, 0.f, 0.f};
    if (t > 0) {
#pragma unroll
        for (int c = 0; c < 4; c++)
            p1[c] = proj[(size_t)(bt - 1) * 256 + 0 * 64 + h * 4 + c];
    }
    float p2[4], q1[4], q2[4];
#pragma unroll
    for (int c = 0; c < 4; c++) {
        p2[c] = proj[(size_t)bt * 256 +  64 + h * 4 + c];
        q1[c] = proj[(size_t)bt * 256 + 128 + h * 4 + c];
        q2[c] = proj[(size_t)bt * 256 + 192 + h * 4 + c];
    }
    float L[6], Jw[6], R[6];
    exterior6(p1, p2, L);
    Jw[0] =  L[5]; Jw[1] = -L[4]; Jw[2] =  L[3];
    Jw[3] =  L[2]; Jw[4] = -L[1]; Jw[5] =  L[0];
    exterior6(q1, q2, R);

    size_t o = ((size_t)(b * HH + h) * TT + t) * 16;
    __nv_bfloat16 hv, lv;
#pragma unroll
    for (int c = 0; c < 6; c++) {
        split1(Jw[c], hv, lv); jwh[o + c] = hv; jwl[o + c] = lv;
        split1(R[c],  hv, lv); r6h[o + c] = hv; r6l[o + c] = lv;
    }
    __nv_bfloat16 z = __float2bfloat16(0.f);
#pragma unroll
    for (int c = 6; c < 16; c++) {
        jwh[o + c] = z; jwl[o + c] = z; r6h[o + c] = z; r6l[o + c] = z;
    }
}

// ---------------- flash attention with incidence bias (HMMA) ----------------
// CTA: 128 threads = 4 warps; 64 q-rows x 64-key tiles; dh = 64.
// smem (bytes):
#define FL_QS_H   0
#define FL_QS_L   9216
#define FL_R6H    18432
#define FL_R6L    21504
#define FL_STAGE0 24576
#define FL_KH 0
#define FL_KL 9216
#define FL_VH 18432
#define FL_VL 27648
#define FL_JH 36864
#define FL_JL 39936
#define FL_STG 43008
#define FLASH2_SMEM (FL_STAGE0 + 2 * FL_STG)   // 110592

__global__ __launch_bounds__(128)
void flash_hmma(const __nv_bfloat16* __restrict__ qkvh,
                const __nv_bfloat16* __restrict__ qkvl,
                const __nv_bfloat16* __restrict__ r6h_g,
                const __nv_bfloat16* __restrict__ r6l_g,
                const __nv_bfloat16* __restrict__ jwh_g,
                const __nv_bfloat16* __restrict__ jwl_g,
                const float* __restrict__ decay_logits,
                const float* __restrict__ bias_scale,
                __nv_bfloat16* __restrict__ oh,
                __nv_bfloat16* __restrict__ ol)
{
    extern __shared__ char smem[];
    const uint32_t sb = smem_u32(smem);
    const int tid = threadIdx.x, lane = tid & 31, w = tid >> 5;
    const int qb = blockIdx.x, bh = blockIdx.y, b = bh >> 4, h = bh & 15;
    const int q0 = qb * 64;

    const float dec = 1.f / (1.f + __expf(-decay_logits[h]));
    const float logd = __logf(dec);
    const float bsc = bias_scale[h];

    // ---- group A: Q tiles (hi/lo) + R6 tiles (hi/lo) ----
#pragma unroll
    for (int i = 0; i < 8; i++) {
        int id = tid + i * 128;
        int arr = id >> 9, row = (id >> 3) & 63, c = id & 7;
        const __nv_bfloat16* src = (arr ? qkvl : qkvh)
            + (size_t)(b * TT + q0 + row) * NQKV + h * 64 + c * 8;
        CP_ASYNC16(sb + (arr ? FL_QS_L : FL_QS_H) + row * 144 + c * 16, src);
    }
#pragma unroll
    for (int i = 0; i < 2; i++) {
        int id = tid + i * 128;
        int arr = id >> 7, row = (id >> 1) & 63, hf = id & 1;
        const __nv_bfloat16* src = (arr ? r6l_g : r6h_g)
            + ((size_t)bh * TT + q0 + row) * 16 + hf * 8;
        CP_ASYNC16(sb + (arr ? FL_R6L : FL_R6H) + row * 48 + hf * 16, src);
    }
    CP_COMMIT();

    auto issue_stage = [&](int kt, int s) {
        const int kt0 = kt * 64;
        const uint32_t stg = sb + FL_STAGE0 + s * FL_STG;
#pragma unroll
        for (int i = 0; i < 16; i++) {
            int id = tid + i * 128;
            int arr = id >> 9, rem = id & 511, row = rem >> 3, c = rem & 7;
            size_t off = (size_t)(b * TT + kt0 + row) * NQKV + h * 64 + c * 8
                       + ((arr & 2) ? 2048 : 1024);
            const __nv_bfloat16* src = ((arr & 1) ? qkvl : qkvh) + off;
            uint32_t dbase = (arr == 0) ? FL_KH : (arr == 1) ? FL_KL : (arr == 2) ? FL_VH : FL_VL;
            CP_ASYNC16(stg + dbase + row * 144 + c * 16, src);
        }
#pragma unroll
        for (int i = 0; i < 2; i++) {
            int id = tid + i * 128;
            int arr = id >> 7, row = (id >> 1) & 63, hf = id & 1;
            const __nv_bfloat16* src = (arr ? jwl_g : jwh_g)
                + ((size_t)bh * TT + kt0 + row) * 16 + hf * 8;
            CP_ASYNC16(stg + (arr ? FL_JL : FL_JH) + row * 48 + hf * 16, src);
        }
        CP_COMMIT();
    };

    issue_stage(0, 0);
    CP_WAIT1();         // Q + R6 done
    __syncthreads();

    // fragment address components (validated in gemm_mma)
    const int amat = lane >> 3, ar = lane & 7;
    const int a_row = (amat & 1) * 8 + ar;
    const int a_colu = amat >> 1;            // 0/1
    const int b_row = (amat >> 1) * 8 + ar;
    const int b_colu = amat & 1;             // 0/1

    // preload r6 A-frags (rank-6 incidence, k16 zero-padded)
    uint32_t r6fh[4], r6fl[4];
    {
        uint32_t ad = sb + FL_R6H + (w * 16 + a_row) * 48 + a_colu * 16;
        LDSM_X4(r6fh[0], r6fh[1], r6fh[2], r6fh[3], ad);
        LDSM_X4(r6fl[0], r6fl[1], r6fl[2], r6fl[3], ad + (FL_R6L - FL_R6H));
    }

    float Oa[8][4];
#pragma unroll
    for (int nt = 0; nt < 8; nt++)
#pragma unroll
        for (int e = 0; e < 4; e++) Oa[nt][e] = 0.f;
    float m0v = -1e30f, m1v = -1e30f, l0v = 0.f, l1v = 0.f;

    const int r0g = q0 + w * 16 + (lane >> 2);
    const int r1g = r0g + 8;
    const int cb = (lane & 3) * 2;
    const int vkey = (lane & 7) + ((lane >> 3) & 1) * 8;
    const int vdo = (lane >> 4) * 8;

    for (int kb = 0; kb <= qb; kb++) {
        const int s = kb & 1;
        if (kb + 1 <= qb) { issue_stage(kb + 1, s ^ 1); CP_WAIT1(); }
        else              { CP_WAIT0(); }
        __syncthreads();
        const uint32_t stg = sb + FL_STAGE0 + s * FL_STG;

        // ---- incidence acc = r6 . Jw^T (hi/lo x3) ----
        float ia[8][4];
#pragma unroll
        for (int nt = 0; nt < 8; nt++)
#pragma unroll
            for (int e = 0; e < 4; e++) ia[nt][e] = 0.f;
#pragma unroll
        for (int nb = 0; nb < 4; nb++) {
            uint32_t jh0, jh1, jh2, jh3, jl0, jl1, jl2, jl3;
            uint32_t jad = stg + FL_JH + (nb * 16 + b_row) * 48 + b_colu * 16;
            LDSM_X4(jh0, jh1, jh2, jh3, jad);
            LDSM_X4(jl0, jl1, jl2, jl3, jad + (FL_JL - FL_JH));
            MMA16816(ia[2*nb],   r6fh, jh0, jh1);
            MMA16816(ia[2*nb],   r6fl, jh0, jh1);
            MMA16816(ia[2*nb],   r6fh, jl0, jl1);
            MMA16816(ia[2*nb+1], r6fh, jh2, jh3);
            MMA16816(ia[2*nb+1], r6fl, jh2, jh3);
            MMA16816(ia[2*nb+1], r6fh, jl2, jl3);
        }

        // ---- S = Q K^T (hi/lo x3) ----
        float sa[8][4];
#pragma unroll
        for (int nt = 0; nt < 8; nt++)
#pragma unroll
            for (int e = 0; e < 4; e++) sa[nt][e] = 0.f;
#pragma unroll
        for (int ks = 0; ks < 4; ks++) {
            uint32_t qf_h[4], qf_l[4];
            uint32_t qad = sb + FL_QS_H + (w * 16 + a_row) * 144 + (ks * 16 + a_colu * 8) * 2;
            LDSM_X4(qf_h[0], qf_h[1], qf_h[2], qf_h[3], qad);
            LDSM_X4(qf_l[0], qf_l[1], qf_l[2], qf_l[3], qad + 9216);
#pragma unroll
            for (int nb = 0; nb < 4; nb++) {
                uint32_t kh0, kh1, kh2, kh3, kl0, kl1, kl2, kl3;
                uint32_t kad = stg + FL_KH + (nb * 16 + b_row) * 144 + (ks * 16 + b_colu * 8) * 2;
                LDSM_X4(kh0, kh1, kh2, kh3, kad);
                LDSM_X4(kl0, kl1, kl2, kl3, kad + 9216);
                MMA16816(sa[2*nb],   qf_h, kh0, kh1);
                MMA16816(sa[2*nb],   qf_h, kl0, kl1);
                MMA16816(sa[2*nb],   qf_l, kh0, kh1);
                MMA16816(sa[2*nb+1], qf_h, kh2, kh3);
                MMA16816(sa[2*nb+1], qf_h, kl2, kl3);
                MMA16816(sa[2*nb+1], qf_l, kh2, kh3);
            }
        }

        // ---- scale + bias + mask + online softmax ----
        const int kt0 = kb * 64;
        float mx0 = -1e30f, mx1 = -1e30f;
#pragma unroll
        for (int nt = 0; nt < 8; nt++) {
#pragma unroll
            for (int e = 0; e < 4; e++) {
                int rg = (e < 2) ? r0g : r1g;
                int kg = kt0 + nt * 8 + cb + (e & 1);
                float sv = sa[nt][e] * 0.125f;
                int diff = rg - kg;
                if (diff < 0) sv = -1e30f;
                else if (diff > 0)
                    sv = fmaf(bsc * __expf(logd * (float)diff), ia[nt][e], sv);
                sa[nt][e] = sv;
                if (e < 2) mx0 = fmaxf(mx0, sv); else mx1 = fmaxf(mx1, sv);
            }
        }
        mx0 = fmaxf(mx0, __shfl_xor_sync(0xffffffffu, mx0, 1));
        mx0 = fmaxf(mx0, __shfl_xor_sync(0xffffffffu, mx0, 2));
        mx1 = fmaxf(mx1, __shfl_xor_sync(0xffffffffu, mx1, 1));
        mx1 = fmaxf(mx1, __shfl_xor_sync(0xffffffffu, mx1, 2));
        float mn0 = fmaxf(m0v, mx0), mn1 = fmaxf(m1v, mx1);
        float al0 = __expf(m0v - mn0), al1 = __expf(m1v - mn1);
        float sum0 = 0.f, sum1 = 0.f;
#pragma unroll
        for (int nt = 0; nt < 8; nt++) {
#pragma unroll
            for (int e = 0; e < 4; e++) {
                float p = __expf(sa[nt][e] - ((e < 2) ? mn0 : mn1));
                sa[nt][e] = p;
                if (e < 2) sum0 += p; else sum1 += p;
            }
        }
        sum0 += __shfl_xor_sync(0xffffffffu, sum0, 1);
        sum0 += __shfl_xor_sync(0xffffffffu, sum0, 2);
        sum1 += __shfl_xor_sync(0xffffffffu, sum1, 1);
        sum1 += __shfl_xor_sync(0xffffffffu, sum1, 2);
        l0v = l0v * al0 + sum0; m0v = mn0;
        l1v = l1v * al1 + sum1; m1v = mn1;
#pragma unroll
        for (int nt = 0; nt < 8; nt++) {
            Oa[nt][0] *= al0; Oa[nt][1] *= al0;
            Oa[nt][2] *= al1; Oa[nt][3] *= al1;
        }

        // ---- O += P V (hi/lo x3) ----
#pragma unroll
        for (int j = 0; j < 4; j++) {
            uint32_t ph[4], pl[4];
            hilo2(sa[2*j][0],   sa[2*j][1],   ph[0], pl[0]);
            hilo2(sa[2*j][2],   sa[2*j][3],   ph[1], pl[1]);
            hilo2(sa[2*j+1][0], sa[2*j+1][1], ph[2], pl[2]);
            hilo2(sa[2*j+1][2], sa[2*j+1][3], ph[3], pl[3]);
#pragma unroll
            for (int nb = 0; nb < 4; nb++) {
                uint32_t vh0, vh1, vh2, vh3, vl0, vl1, vl2, vl3;
                uint32_t vad = stg + FL_VH + (16 * j + vkey) * 144 + (nb * 16 + vdo) * 2;
                LDSM_X4_T(vh0, vh1, vh2, vh3, vad);
                LDSM_X4_T(vl0, vl1, vl2, vl3, vad + 9216);
                MMA16816(Oa[2*nb],   ph, vh0, vh1);
                MMA16816(Oa[2*nb],   pl, vh0, vh1);
                MMA16816(Oa[2*nb],   ph, vl0, vl1);
                MMA16816(Oa[2*nb+1], ph, vh2, vh3);
                MMA16816(Oa[2*nb+1], pl, vh2, vh3);
                MMA16816(Oa[2*nb+1], ph, vl2, vl3);
            }
        }
        __syncthreads();
    }

    // ---- normalize + write attn hi/lo bf16: out[b, q, h*64 + d] ----
    const float inv0 = 1.f / l0v, inv1 = 1.f / l1v;
#pragma unroll
    for (int nt = 0; nt < 8; nt++) {
        int dcol = nt * 8 + cb;
        size_t o0 = (size_t)(b * TT + r0g) * DD + h * 64 + dcol;
        size_t o1 = (size_t)(b * TT + r1g) * DD + h * 64 + dcol;
        uint32_t hv, lv;
        hilo2(Oa[nt][0] * inv0, Oa[nt][1] * inv0, hv, lv);
        *(uint32_t*)(oh + o0) = hv; *(uint32_t*)(ol + o0) = lv;
        hilo2(Oa[nt][2] * inv1, Oa[nt][3] * inv1, hv, lv);
        *(uint32_t*)(oh + o1) = hv; *(uint32_t*)(ol + o1) = lv;
    }
}

// ---------------- launch ----------------
extern "C" void kernel_launch(void* const* d_in, const int* in_sizes, int n_in,
                              void* d_out, int out_size)
{
    const float* x      = (const float*)d_in[0];
    const float* w_qkv  = (const float*)d_in[1];
    const float* b_qkv  = (const float*)d_in[2];
    const float* w1w    = (const float*)d_in[3];
    const float* w2w    = (const float*)d_in[4];
    const float* w1r    = (const float*)d_in[5];
    const float* w2r    = (const float*)d_in[6];
    const float* w_out  = (const float*)d_in[7];
    const float* b_out  = (const float*)d_in[8];
    const float* dl     = (const float*)d_in[9];
    const float* bs     = (const float*)d_in[10];

    float* projp;
    __nv_bfloat16 *xh, *xl, *wqh, *wql, *woh, *wol, *ath, *atl;
    __nv_bfloat16 *qkvh, *qkvl, *r6h, *r6l, *jwh, *jwl;
    cudaGetSymbolAddress((void**)&projp, g_proj);
    cudaGetSymbolAddress((void**)&xh,  g_x_hi);
    cudaGetSymbolAddress((void**)&xl,  g_x_lo);
    cudaGetSymbolAddress((void**)&wqh, g_wqkv_hi);
    cudaGetSymbolAddress((void**)&wql, g_wqkv_lo);
    cudaGetSymbolAddress((void**)&woh, g_wout_hi);
    cudaGetSymbolAddress((void**)&wol, g_wout_lo);
    cudaGetSymbolAddress((void**)&ath, g_attn_hi);
    cudaGetSymbolAddress((void**)&atl, g_attn_lo);
    cudaGetSymbolAddress((void**)&qkvh, g_qkv_hi);
    cudaGetSymbolAddress((void**)&qkvl, g_qkv_lo);
    cudaGetSymbolAddress((void**)&r6h, g_r6_hi);
    cudaGetSymbolAddress((void**)&r6l, g_r6_lo);
    cudaGetSymbolAddress((void**)&jwh, g_jw_hi);
    cudaGetSymbolAddress((void**)&jwl, g_jw_lo);

    cudaFuncSetAttribute(gemm_mma, cudaFuncAttributeMaxDynamicSharedMemorySize, GEMM_SMEM);
    cudaFuncSetAttribute(flash_hmma, cudaFuncAttributeMaxDynamicSharedMemorySize, FLASH2_SMEM);

    // 0. hi/lo splits of inputs
    {
        int n4;
        n4 = (MM * DD) / 4;
        split_kernel<<<(n4 + 255) / 256, 256>>>(x, xh, xl, n4);
        n4 = (NQKV * DD) / 4;
        split_kernel<<<(n4 + 255) / 256, 256>>>(w_qkv, wqh, wql, n4);
        n4 = (DD * DD) / 4;
        split_kernel<<<(n4 + 255) / 256, 256>>>(w_out, woh, wol, n4);
    }
    // 1. QKV projection -> bf16 hi/lo directly
    {
        dim3 grid(NQKV / 128, MM / 128);
        gemm_mma<<<grid, 256, GEMM_SMEM>>>(xh, xl, wqh, wql, b_qkv,
                                           nullptr, qkvh, qkvl, NQKV, DD);
    }
    // 2. four small projections (fp32)
    {
        WP wp;
        wp.w[0] = w1w; wp.w[1] = w2w; wp.w[2] = w1r; wp.w[3] = w2r;
        dim3 grid(4, MM / 128);
        proj_gemm<<<grid, 256>>>(x, wp, projp, DD);
    }
    // 3. Plücker lines + J6 -> bf16 hi/lo padded-16
    {
        int n = BB * TT * HH;
        lines_kernel<<<(n + 255) / 256, 256>>>(projp, r6h, r6l, jwh, jwl);
    }
    // 4. flash attention (HMMA) -> attn hi/lo
    {
        dim3 grid(TT / 64, BB * HH);
        flash_hmma<<<grid, 128, FLASH2_SMEM>>>(qkvh, qkvl, r6h, r6l, jwh, jwl,
                                               dl, bs, ath, atl);
    }
    // 5. output projection (fp32 out + bias)
    {
        dim3 grid(DD / 128, MM / 128);
        gemm_mma<<<grid, 256, GEMM_SMEM>>>(ath, atl, woh, wol, b_out,
                                           (float*)d_out, nullptr, nullptr, DD, DD);
    }
}